// round 1
// baseline (speedup 1.0000x reference)
#include <cuda_runtime.h>
#include <cstddef>

#define Bn   2
#define Ln   2048
#define Hn   768
#define DIn  1536
#define Nn   16
#define Rn   48
#define BLn  (Bn*Ln)     /* 4096 */
#define SP   (Rn + 2*Nn) /* 80 */

// -------- scratch (static device globals; no allocation allowed) --------
__device__ float g_proj[(size_t)BLn * 2 * DIn];   // [4096][3072]  in_proj output (h | gate)
__device__ float g_h   [(size_t)BLn * DIn];       // [4096][1536]  conv+silu output (time-major)
__device__ float g_ssm [(size_t)BLn * SP];        // [4096][80]    x_proj output (dt_raw|B|C)
__device__ float g_dt  [(size_t)BLn * DIn];       // [4096][1536]  softplus(dt)
__device__ float g_y   [(size_t)BLn * DIn];       // [4096][1536]  scan output (post skip+gate)

__device__ __forceinline__ float sigmoidf_(float x) { return 1.f / (1.f + __expf(-x)); }

// ============================================================================
// Generic fp32 GEMM: C[M,N] = A[M,K](lda) @ B[K,N], M = 4096, tiles 128x128x8.
// EPI==1: C = softplus(C + bias[n])
// ============================================================================
template<int EPI>
__global__ __launch_bounds__(256)
void sgemm128(const float* __restrict__ A, int lda,
              const float* __restrict__ Bm,
              float* __restrict__ C,
              int N, int K,
              const float* __restrict__ bias)
{
    __shared__ float As[2][8][128];
    __shared__ float Bs[2][8][128];

    const int tid  = threadIdx.x;
    const int bm   = blockIdx.y << 7;
    const int bn   = blockIdx.x << 7;
    const int arow = tid >> 1;            // 0..127
    const int acol = (tid & 1) << 2;      // 0 or 4
    const int brow = tid >> 5;            // 0..7
    const int bcol = (tid & 31) << 2;     // 0..124
    const int tx   = tid & 15;
    const int ty   = tid >> 4;
    const int tm0  = ty << 3;
    const int tn0  = tx << 3;

    const float* Ap = A + (size_t)(bm + arow) * lda + acol;
    const float* Bp = Bm + (size_t)brow * N + bn + bcol;

    float acc[8][8];
#pragma unroll
    for (int i = 0; i < 8; i++)
#pragma unroll
        for (int j = 0; j < 8; j++) acc[i][j] = 0.f;

    const int nk = K >> 3;

    // prologue: tile 0
    {
        float4 a4 = *(const float4*)Ap;
        float4 b4 = *(const float4*)Bp;
        As[0][acol + 0][arow] = a4.x;
        As[0][acol + 1][arow] = a4.y;
        As[0][acol + 2][arow] = a4.z;
        As[0][acol + 3][arow] = a4.w;
        *(float4*)&Bs[0][brow][bcol] = b4;
    }
    __syncthreads();

    for (int kt = 0; kt < nk; ++kt) {
        const int buf = kt & 1;
        float4 a4n, b4n;
        const bool more = (kt + 1 < nk);
        if (more) {
            a4n = *(const float4*)(Ap + (kt + 1) * 8);
            b4n = *(const float4*)(Bp + (size_t)(kt + 1) * 8 * N);
        }
#pragma unroll
        for (int k = 0; k < 8; k++) {
            float4 x0 = *(const float4*)&As[buf][k][tm0];
            float4 x1 = *(const float4*)&As[buf][k][tm0 + 4];
            float4 y0 = *(const float4*)&Bs[buf][k][tn0];
            float4 y1 = *(const float4*)&Bs[buf][k][tn0 + 4];
            float ra[8] = {x0.x, x0.y, x0.z, x0.w, x1.x, x1.y, x1.z, x1.w};
            float rb[8] = {y0.x, y0.y, y0.z, y0.w, y1.x, y1.y, y1.z, y1.w};
#pragma unroll
            for (int i = 0; i < 8; i++)
#pragma unroll
                for (int j = 0; j < 8; j++)
                    acc[i][j] = fmaf(ra[i], rb[j], acc[i][j]);
        }
        if (more) {
            const int nb = buf ^ 1;
            As[nb][acol + 0][arow] = a4n.x;
            As[nb][acol + 1][arow] = a4n.y;
            As[nb][acol + 2][arow] = a4n.z;
            As[nb][acol + 3][arow] = a4n.w;
            *(float4*)&Bs[nb][brow][bcol] = b4n;
        }
        __syncthreads();
    }

    float bvals[8];
    if (EPI == 1) {
#pragma unroll
        for (int j = 0; j < 8; j++) bvals[j] = bias[bn + tn0 + j];
    }
#pragma unroll
    for (int i = 0; i < 8; i++) {
        float* crow = C + (size_t)(bm + tm0 + i) * N + bn + tn0;
        float o[8];
#pragma unroll
        for (int j = 0; j < 8; j++) {
            float v = acc[i][j];
            if (EPI == 1) {
                v += bvals[j];
                // softplus: max(x,0) + log1p(exp(-|x|))
                v = fmaxf(v, 0.f) + log1pf(__expf(-fabsf(v)));
            }
            o[j] = v;
        }
        *(float4*)crow       = make_float4(o[0], o[1], o[2], o[3]);
        *(float4*)(crow + 4) = make_float4(o[4], o[5], o[6], o[7]);
    }
}

// ============================================================================
// Depthwise causal conv (K=4) + bias + SiLU.
// reads g_proj (h half), writes g_h[b*L+t][d]
// ============================================================================
__global__ __launch_bounds__(256)
void conv_silu(const float* __restrict__ proj,
               const float* __restrict__ cw,
               const float* __restrict__ cb,
               float* __restrict__ h)
{
    int idx = blockIdx.x * blockDim.x + threadIdx.x;   // 0 .. BLn*DIn-1
    int d  = idx % DIn;
    int bt = idx / DIn;
    int t  = bt % Ln;

    float4 w = *(const float4*)(cw + d * 4);   // conv_w[d,0,0..3]
    float acc = cb[d];
    const float* p = proj + (size_t)bt * (2 * DIn) + d;
    const int s = 2 * DIn;
    if (t >= 3) acc = fmaf(p[-3 * s], w.x, acc);
    if (t >= 2) acc = fmaf(p[-2 * s], w.y, acc);
    if (t >= 1) acc = fmaf(p[-1 * s], w.z, acc);
    acc = fmaf(p[0], w.w, acc);
    h[idx] = acc * sigmoidf_(acc);
}

// ============================================================================
// x_proj GEMM: ssm[4096,80] = h[4096,1536] @ W[1536,80]. BM=32, BK=16.
// ============================================================================
__global__ __launch_bounds__(256)
void gemm_xproj(const float* __restrict__ A,
                const float* __restrict__ W,
                float* __restrict__ C)
{
    __shared__ float As[2][16][32];
    __shared__ float Ws[2][16][SP];

    const int tid = threadIdx.x;
    const int bm  = blockIdx.x << 5;
    const int ar  = tid >> 3;           // 0..31
    const int ac  = (tid & 7) << 1;     // 0..14
    const int tx  = tid & 15;           // cols tx*5 .. tx*5+4
    const int ty  = tid >> 4;           // rows ty*2, ty*2+1

    float acc[2][5];
#pragma unroll
    for (int i = 0; i < 2; i++)
#pragma unroll
        for (int j = 0; j < 5; j++) acc[i][j] = 0.f;

    const float* Ap = A + (size_t)(bm + ar) * DIn + ac;
    const int nk = DIn / 16;   // 96

    {
        float2 a2 = *(const float2*)Ap;
        As[0][ac][ar]     = a2.x;
        As[0][ac + 1][ar] = a2.y;
#pragma unroll
        for (int j = 0; j < 5; j++) {
            int e = tid + (j << 8);
            int k = e / SP, n2 = e % SP;
            Ws[0][k][n2] = W[k * SP + n2];
        }
    }
    __syncthreads();

    for (int kt = 0; kt < nk; ++kt) {
        const int buf = kt & 1;
        const bool more = (kt + 1 < nk);
        float2 a2n;
        float  wn[5];
        if (more) {
            a2n = *(const float2*)(Ap + (kt + 1) * 16);
#pragma unroll
            for (int j = 0; j < 5; j++) {
                int e = tid + (j << 8);
                int k = e / SP, n2 = e % SP;
                wn[j] = W[((kt + 1) * 16 + k) * SP + n2];
            }
        }
#pragma unroll
        for (int k = 0; k < 16; k++) {
            float rA0 = As[buf][k][ty * 2];
            float rA1 = As[buf][k][ty * 2 + 1];
#pragma unroll
            for (int j = 0; j < 5; j++) {
                float w = Ws[buf][k][tx * 5 + j];
                acc[0][j] = fmaf(rA0, w, acc[0][j]);
                acc[1][j] = fmaf(rA1, w, acc[1][j]);
            }
        }
        if (more) {
            const int nb = buf ^ 1;
            As[nb][ac][ar]     = a2n.x;
            As[nb][ac + 1][ar] = a2n.y;
#pragma unroll
            for (int j = 0; j < 5; j++) {
                int e = tid + (j << 8);
                int k = e / SP, n2 = e % SP;
                Ws[nb][k][n2] = wn[j];
            }
        }
        __syncthreads();
    }

#pragma unroll
    for (int i = 0; i < 2; i++)
#pragma unroll
        for (int j = 0; j < 5; j++)
            C[(size_t)(bm + ty * 2 + i) * SP + tx * 5 + j] = acc[i][j];
}

// ============================================================================
// Fused selective scan + skip + gating.
// lane layout: warp w handles channels d0+2w, d0+2w+1; lane&15 = state index n.
// Time processed in 32-step smem double-buffered chunks.
// ============================================================================
__global__ __launch_bounds__(128)
void scan_kernel(const float* __restrict__ Alog, const float* __restrict__ Dp)
{
    __shared__ float s_h [2][32][8];
    __shared__ float s_dt[2][32][8];
    __shared__ float s_g [2][32][8];
    __shared__ float s_B [2][32][16];
    __shared__ float s_C [2][32][16];

    const int tid  = threadIdx.x;
    const int lane = tid & 31;
    const int w    = tid >> 5;
    const int n    = lane & 15;
    const int half = lane >> 4;
    const int dl   = (w << 1) + half;                 // 0..7
    const int blk  = blockIdx.x;
    const int b    = blk / (DIn / 8);
    const int d0   = (blk % (DIn / 8)) << 3;
    const int d    = d0 + dl;
    const int bL   = b * Ln;

    const float A_dn = -__expf(Alog[d * Nn + n]);
    const float Dv   = Dp[d];
    float state = 0.f;

    float rh[2], rdt[2], rg[2], rB[4], rC[4];

    auto do_load = [&](int c) {
        int t0 = c << 5;
#pragma unroll
        for (int j = 0; j < 2; j++) {
            int e = tid + (j << 7);
            int t = e >> 3, dd = e & 7;
            int row = bL + t0 + t;
            rh[j]  = g_h [(size_t)row * DIn + d0 + dd];
            rdt[j] = g_dt[(size_t)row * DIn + d0 + dd];
            rg[j]  = g_proj[(size_t)row * (2 * DIn) + DIn + d0 + dd];
        }
#pragma unroll
        for (int j = 0; j < 4; j++) {
            int e = tid + (j << 7);
            int t = e >> 4, nn = e & 15;
            int row = bL + t0 + t;
            rB[j] = g_ssm[(size_t)row * SP + Rn + nn];
            rC[j] = g_ssm[(size_t)row * SP + Rn + Nn + nn];
        }
    };
    auto do_store = [&](int buf) {
#pragma unroll
        for (int j = 0; j < 2; j++) {
            int e = tid + (j << 7);
            int t = e >> 3, dd = e & 7;
            s_h [buf][t][dd] = rh[j];
            s_dt[buf][t][dd] = rdt[j];
            s_g [buf][t][dd] = rg[j];
        }
#pragma unroll
        for (int j = 0; j < 4; j++) {
            int e = tid + (j << 7);
            int t = e >> 4, nn = e & 15;
            s_B[buf][t][nn] = rB[j];
            s_C[buf][t][nn] = rC[j];
        }
    };

    do_load(0);
    do_store(0);
    __syncthreads();

    const int NC = Ln / 32;   // 64 chunks
    for (int c = 0; c < NC; c++) {
        const int buf = c & 1;
        if (c + 1 < NC) do_load(c + 1);
        const int t0 = c << 5;
#pragma unroll 8
        for (int t = 0; t < 32; t++) {
            float dtv = s_dt[buf][t][dl];
            float hv  = s_h [buf][t][dl];
            float Bv  = s_B [buf][t][n];
            float Cv  = s_C [buf][t][n];
            float dA  = __expf(A_dn * dtv);
            state = fmaf(dA, state, Bv * hv);
            float p = state * Cv;
            p += __shfl_xor_sync(0xffffffffu, p, 8);
            p += __shfl_xor_sync(0xffffffffu, p, 4);
            p += __shfl_xor_sync(0xffffffffu, p, 2);
            p += __shfl_xor_sync(0xffffffffu, p, 1);
            if (n == 0) {
                float gv = s_g[buf][t][dl];
                float yv = (p + hv * Dv) * gv * sigmoidf_(gv);
                g_y[(size_t)(bL + t0 + t) * DIn + d] = yv;
            }
        }
        if (c + 1 < NC) do_store(buf ^ 1);
        __syncthreads();
    }
}

// ============================================================================
extern "C" void kernel_launch(void* const* d_in, const int* in_sizes, int n_in,
                              void* d_out, int out_size)
{
    const float* x          = (const float*)d_in[0];
    const float* in_proj_w  = (const float*)d_in[1];
    const float* conv_w     = (const float*)d_in[2];
    const float* conv_b     = (const float*)d_in[3];
    const float* x_proj_w   = (const float*)d_in[4];
    const float* dt_proj_w  = (const float*)d_in[5];
    const float* dt_proj_b  = (const float*)d_in[6];
    const float* out_proj_w = (const float*)d_in[7];
    const float* A_log      = (const float*)d_in[8];
    const float* D_param    = (const float*)d_in[9];
    float* out = (float*)d_out;

    float *proj, *h, *ssm, *dt, *y;
    cudaGetSymbolAddress((void**)&proj, g_proj);
    cudaGetSymbolAddress((void**)&h,    g_h);
    cudaGetSymbolAddress((void**)&ssm,  g_ssm);
    cudaGetSymbolAddress((void**)&dt,   g_dt);
    cudaGetSymbolAddress((void**)&y,    g_y);

    // 1) proj = x @ in_proj_w                      [4096,3072], K=768
    sgemm128<0><<<dim3((2 * DIn) / 128, BLn / 128), 256>>>(
        x, Hn, in_proj_w, proj, 2 * DIn, Hn, nullptr);

    // 2) depthwise causal conv + SiLU -> g_h       [4096,1536]
    conv_silu<<<(BLn * DIn) / 256, 256>>>(proj, conv_w, conv_b, h);

    // 3) ssm = h @ x_proj_w                        [4096,80], K=1536
    gemm_xproj<<<BLn / 32, 256>>>(h, x_proj_w, ssm);

    // 4) dt = softplus(ssm[:, :48] @ dt_proj_w + b) [4096,1536], K=48
    sgemm128<1><<<dim3(DIn / 128, BLn / 128), 256>>>(
        ssm, SP, dt_proj_w, dt, DIn, Rn, dt_proj_b);

    // 5) selective scan (+ skip + gating) -> g_y   [4096,1536]
    scan_kernel<<<Bn * (DIn / 8), 128>>>(A_log, D_param);

    // 6) out = y @ out_proj_w                      [4096,768], K=1536
    sgemm128<0><<<dim3(Hn / 128, BLn / 128), 256>>>(
        y, DIn, out_proj_w, out, Hn, DIn, nullptr);
}

// round 2
// speedup vs baseline: 1.6041x; 1.6041x over previous
#include <cuda_runtime.h>
#include <cstdint>
#include <cstddef>

#define Bn   2
#define Ln   2048
#define Hn   768
#define DIn  1536
#define Nn   16
#define Rn   48
#define BLn  (Bn*Ln)     /* 4096 */
#define SP   (Rn + 2*Nn) /* 80 */

// -------- scratch (static device globals; no allocation allowed) --------
__device__ float g_proj[(size_t)BLn * 2 * DIn];   // [4096][3072]  in_proj output (h | gate)
__device__ float g_h   [(size_t)BLn * DIn];       // [4096][1536]  conv+silu output
__device__ float g_ssm [(size_t)BLn * SP];        // [4096][80]    x_proj output (dt_raw|B|C)
__device__ float g_dt  [(size_t)BLn * DIn];       // [4096][1536]  softplus(dt)
__device__ float g_y   [(size_t)BLn * DIn];       // [4096][1536]  scan output (post skip+gate)

__device__ __forceinline__ float sigmoidf_(float x) { return 1.f / (1.f + __expf(-x)); }
__device__ __forceinline__ uint32_t f2tf(float f) {
    uint32_t u; asm("cvt.rna.tf32.f32 %0, %1;" : "=r"(u) : "f"(f)); return u;
}
__device__ __forceinline__ float softplusf_(float x) {
    return fmaxf(x, 0.f) + log1pf(__expf(-fabsf(x)));
}

// ============================================================================
// TF32 tensor-core GEMM: C[M,N] = A[M,K](lda) @ B[K,N].
// Block tile 128x128, BK=16, 8 warps (each 64x32 via 4x4 m16n8k8 MMAs).
// EPI==1: C = softplus(C + bias[n])
// Requires: M%128==0, N%128==0, K%16==0.
// ============================================================================
template<int EPI>
__global__ __launch_bounds__(256, 2)
void tgemm(const float* __restrict__ A, int lda,
           const float* __restrict__ Bm,
           float* __restrict__ C, int N, int K,
           const float* __restrict__ bias)
{
    // A stored [m][k] with row stride 20 (conflict-free frag reads: (20m+k)%32 distinct)
    // B stored [k][n] with row stride 136 ((8k+n)%32 distinct)
    __shared__ uint32_t As[2][128][20];
    __shared__ uint32_t Bs[2][16][136];

    const int tid  = threadIdx.x;
    const int lane = tid & 31;
    const int warp = tid >> 5;
    const int wm   = warp >> 2;      // 0..1
    const int wn   = warp & 3;       // 0..3
    const int m0   = wm * 64;
    const int n0   = wn * 32;
    const int g    = lane >> 2;      // 0..7
    const int c    = lane & 3;       // 0..3

    const int bm = blockIdx.y << 7;
    const int bn = blockIdx.x << 7;

    // global->smem mapping
    const int ar = tid >> 2;            // 0..63 (row), second load +64
    const int ac = (tid & 3) << 2;      // 0,4,8,12 (k within tile)
    const int br = tid >> 5;            // 0..7 (k row), second load +8
    const int bc = (tid & 31) << 2;     // 0..124 (n)

    const float* Ap0 = A + (size_t)(bm + ar) * lda + ac;
    const float* Ap1 = Ap0 + (size_t)64 * lda;
    const float* Bp0 = Bm + (size_t)br * N + bn + bc;
    const float* Bp1 = Bp0 + (size_t)8 * N;

    float acc[4][4][4];
#pragma unroll
    for (int i = 0; i < 4; i++)
#pragma unroll
        for (int j = 0; j < 4; j++)
#pragma unroll
            for (int q = 0; q < 4; q++) acc[i][j][q] = 0.f;

    float4 aR0, aR1, bR0, bR1;

    auto g2r = [&](int kt) {
        const int k0 = kt << 4;
        aR0 = *(const float4*)(Ap0 + k0);
        aR1 = *(const float4*)(Ap1 + k0);
        bR0 = *(const float4*)(Bp0 + (size_t)k0 * N);
        bR1 = *(const float4*)(Bp1 + (size_t)k0 * N);
    };
    auto r2s = [&](int buf) {
        uint4 a0 = make_uint4(f2tf(aR0.x), f2tf(aR0.y), f2tf(aR0.z), f2tf(aR0.w));
        uint4 a1 = make_uint4(f2tf(aR1.x), f2tf(aR1.y), f2tf(aR1.z), f2tf(aR1.w));
        *(uint4*)&As[buf][ar][ac]      = a0;
        *(uint4*)&As[buf][ar + 64][ac] = a1;
        uint4 b0 = make_uint4(f2tf(bR0.x), f2tf(bR0.y), f2tf(bR0.z), f2tf(bR0.w));
        uint4 b1 = make_uint4(f2tf(bR1.x), f2tf(bR1.y), f2tf(bR1.z), f2tf(bR1.w));
        *(uint4*)&Bs[buf][br][bc]     = b0;
        *(uint4*)&Bs[buf][br + 8][bc] = b1;
    };
    auto compute = [&](int buf) {
#pragma unroll
        for (int ks = 0; ks < 2; ks++) {
            const int kb = ks << 3;
            uint32_t af[4][4], bf[4][2];
#pragma unroll
            for (int i = 0; i < 4; i++) {
                const int r = m0 + i * 16 + g;
                af[i][0] = As[buf][r][kb + c];
                af[i][1] = As[buf][r + 8][kb + c];
                af[i][2] = As[buf][r][kb + c + 4];
                af[i][3] = As[buf][r + 8][kb + c + 4];
            }
#pragma unroll
            for (int j = 0; j < 4; j++) {
                const int col = n0 + j * 8 + g;
                bf[j][0] = Bs[buf][kb + c][col];
                bf[j][1] = Bs[buf][kb + c + 4][col];
            }
#pragma unroll
            for (int i = 0; i < 4; i++)
#pragma unroll
                for (int j = 0; j < 4; j++)
                    asm volatile(
                        "mma.sync.aligned.m16n8k8.row.col.f32.tf32.tf32.f32 "
                        "{%0,%1,%2,%3}, {%4,%5,%6,%7}, {%8,%9}, {%0,%1,%2,%3};\n"
                        : "+f"(acc[i][j][0]), "+f"(acc[i][j][1]),
                          "+f"(acc[i][j][2]), "+f"(acc[i][j][3])
                        : "r"(af[i][0]), "r"(af[i][1]), "r"(af[i][2]), "r"(af[i][3]),
                          "r"(bf[j][0]), "r"(bf[j][1]));
        }
    };

    const int nk = K >> 4;
    g2r(0);
    r2s(0);
    __syncthreads();

    for (int kt = 0; kt < nk; ++kt) {
        const int buf = kt & 1;
        const bool more = (kt + 1 < nk);
        if (more) g2r(kt + 1);
        compute(buf);
        if (more) r2s(buf ^ 1);
        __syncthreads();
    }

    // epilogue
#pragma unroll
    for (int i = 0; i < 4; i++) {
        const int r0 = bm + m0 + i * 16 + g;
#pragma unroll
        for (int j = 0; j < 4; j++) {
            const int col = bn + n0 + j * 8 + 2 * c;
            float v00 = acc[i][j][0], v01 = acc[i][j][1];
            float v10 = acc[i][j][2], v11 = acc[i][j][3];
            if (EPI == 1) {
                const float b0v = bias[col], b1v = bias[col + 1];
                v00 = softplusf_(v00 + b0v);
                v01 = softplusf_(v01 + b1v);
                v10 = softplusf_(v10 + b0v);
                v11 = softplusf_(v11 + b1v);
            }
            *(float2*)&C[(size_t)r0 * N + col]       = make_float2(v00, v01);
            *(float2*)&C[(size_t)(r0 + 8) * N + col] = make_float2(v10, v11);
        }
    }
}

// ============================================================================
// Depthwise causal conv (K=4) + bias + SiLU.
// ============================================================================
__global__ __launch_bounds__(256)
void conv_silu(const float* __restrict__ proj,
               const float* __restrict__ cw,
               const float* __restrict__ cb,
               float* __restrict__ h)
{
    int idx = blockIdx.x * blockDim.x + threadIdx.x;
    int d  = idx % DIn;
    int bt = idx / DIn;
    int t  = bt % Ln;

    float4 w = *(const float4*)(cw + d * 4);
    float acc = cb[d];
    const float* p = proj + (size_t)bt * (2 * DIn) + d;
    const int s = 2 * DIn;
    if (t >= 3) acc = fmaf(p[-3 * s], w.x, acc);
    if (t >= 2) acc = fmaf(p[-2 * s], w.y, acc);
    if (t >= 1) acc = fmaf(p[-1 * s], w.z, acc);
    acc = fmaf(p[0], w.w, acc);
    h[idx] = acc * sigmoidf_(acc);
}

// ============================================================================
// x_proj GEMM: ssm[4096,80] = h[4096,1536] @ W[1536,80]. BM=32, BK=16.
// ============================================================================
__global__ __launch_bounds__(256)
void gemm_xproj(const float* __restrict__ A,
                const float* __restrict__ W,
                float* __restrict__ C)
{
    __shared__ float As[2][16][32];
    __shared__ float Ws[2][16][SP];

    const int tid = threadIdx.x;
    const int bm  = blockIdx.x << 5;
    const int ar  = tid >> 3;
    const int ac  = (tid & 7) << 1;
    const int tx  = tid & 15;
    const int ty  = tid >> 4;

    float acc[2][5];
#pragma unroll
    for (int i = 0; i < 2; i++)
#pragma unroll
        for (int j = 0; j < 5; j++) acc[i][j] = 0.f;

    const float* Ap = A + (size_t)(bm + ar) * DIn + ac;
    const int nk = DIn / 16;

    {
        float2 a2 = *(const float2*)Ap;
        As[0][ac][ar]     = a2.x;
        As[0][ac + 1][ar] = a2.y;
#pragma unroll
        for (int j = 0; j < 5; j++) {
            int e = tid + (j << 8);
            int k = e / SP, n2 = e % SP;
            Ws[0][k][n2] = W[k * SP + n2];
        }
    }
    __syncthreads();

    for (int kt = 0; kt < nk; ++kt) {
        const int buf = kt & 1;
        const bool more = (kt + 1 < nk);
        float2 a2n;
        float  wn[5];
        if (more) {
            a2n = *(const float2*)(Ap + (kt + 1) * 16);
#pragma unroll
            for (int j = 0; j < 5; j++) {
                int e = tid + (j << 8);
                int k = e / SP, n2 = e % SP;
                wn[j] = W[((kt + 1) * 16 + k) * SP + n2];
            }
        }
#pragma unroll
        for (int k = 0; k < 16; k++) {
            float rA0 = As[buf][k][ty * 2];
            float rA1 = As[buf][k][ty * 2 + 1];
#pragma unroll
            for (int j = 0; j < 5; j++) {
                float w = Ws[buf][k][tx * 5 + j];
                acc[0][j] = fmaf(rA0, w, acc[0][j]);
                acc[1][j] = fmaf(rA1, w, acc[1][j]);
            }
        }
        if (more) {
            const int nb = buf ^ 1;
            As[nb][ac][ar]     = a2n.x;
            As[nb][ac + 1][ar] = a2n.y;
#pragma unroll
            for (int j = 0; j < 5; j++) {
                int e = tid + (j << 8);
                int k = e / SP, n2 = e % SP;
                Ws[nb][k][n2] = wn[j];
            }
        }
        __syncthreads();
    }

#pragma unroll
    for (int i = 0; i < 2; i++)
#pragma unroll
        for (int j = 0; j < 5; j++)
            C[(size_t)(bm + ty * 2 + i) * SP + tx * 5 + j] = acc[i][j];
}

// ============================================================================
// Fused selective scan + skip + gating.
// ============================================================================
__global__ __launch_bounds__(128)
void scan_kernel(const float* __restrict__ Alog, const float* __restrict__ Dp)
{
    __shared__ float s_h [2][32][8];
    __shared__ float s_dt[2][32][8];
    __shared__ float s_g [2][32][8];
    __shared__ float s_B [2][32][16];
    __shared__ float s_C [2][32][16];

    const int tid  = threadIdx.x;
    const int lane = tid & 31;
    const int w    = tid >> 5;
    const int n    = lane & 15;
    const int half = lane >> 4;
    const int dl   = (w << 1) + half;
    const int blk  = blockIdx.x;
    const int b    = blk / (DIn / 8);
    const int d0   = (blk % (DIn / 8)) << 3;
    const int d    = d0 + dl;
    const int bL   = b * Ln;

    const float A_dn = -__expf(Alog[d * Nn + n]);
    const float Dv   = Dp[d];
    float state = 0.f;

    float rh[2], rdt[2], rg[2], rB[4], rC[4];

    auto do_load = [&](int c) {
        int t0 = c << 5;
#pragma unroll
        for (int j = 0; j < 2; j++) {
            int e = tid + (j << 7);
            int t = e >> 3, dd = e & 7;
            int row = bL + t0 + t;
            rh[j]  = g_h [(size_t)row * DIn + d0 + dd];
            rdt[j] = g_dt[(size_t)row * DIn + d0 + dd];
            rg[j]  = g_proj[(size_t)row * (2 * DIn) + DIn + d0 + dd];
        }
#pragma unroll
        for (int j = 0; j < 4; j++) {
            int e = tid + (j << 7);
            int t = e >> 4, nn = e & 15;
            int row = bL + t0 + t;
            rB[j] = g_ssm[(size_t)row * SP + Rn + nn];
            rC[j] = g_ssm[(size_t)row * SP + Rn + Nn + nn];
        }
    };
    auto do_store = [&](int buf) {
#pragma unroll
        for (int j = 0; j < 2; j++) {
            int e = tid + (j << 7);
            int t = e >> 3, dd = e & 7;
            s_h [buf][t][dd] = rh[j];
            s_dt[buf][t][dd] = rdt[j];
            s_g [buf][t][dd] = rg[j];
        }
#pragma unroll
        for (int j = 0; j < 4; j++) {
            int e = tid + (j << 7);
            int t = e >> 4, nn = e & 15;
            s_B[buf][t][nn] = rB[j];
            s_C[buf][t][nn] = rC[j];
        }
    };

    do_load(0);
    do_store(0);
    __syncthreads();

    const int NC = Ln / 32;
    for (int c = 0; c < NC; c++) {
        const int buf = c & 1;
        if (c + 1 < NC) do_load(c + 1);
        const int t0 = c << 5;
#pragma unroll 8
        for (int t = 0; t < 32; t++) {
            float dtv = s_dt[buf][t][dl];
            float hv  = s_h [buf][t][dl];
            float Bv  = s_B [buf][t][n];
            float Cv  = s_C [buf][t][n];
            float dA  = __expf(A_dn * dtv);
            state = fmaf(dA, state, Bv * hv);
            float p = state * Cv;
            p += __shfl_xor_sync(0xffffffffu, p, 8);
            p += __shfl_xor_sync(0xffffffffu, p, 4);
            p += __shfl_xor_sync(0xffffffffu, p, 2);
            p += __shfl_xor_sync(0xffffffffu, p, 1);
            if (n == 0) {
                float gv = s_g[buf][t][dl];
                float yv = (p + hv * Dv) * gv * sigmoidf_(gv);
                g_y[(size_t)(bL + t0 + t) * DIn + d] = yv;
            }
        }
        if (c + 1 < NC) do_store(buf ^ 1);
        __syncthreads();
    }
}

// ============================================================================
extern "C" void kernel_launch(void* const* d_in, const int* in_sizes, int n_in,
                              void* d_out, int out_size)
{
    const float* x          = (const float*)d_in[0];
    const float* in_proj_w  = (const float*)d_in[1];
    const float* conv_w     = (const float*)d_in[2];
    const float* conv_b     = (const float*)d_in[3];
    const float* x_proj_w   = (const float*)d_in[4];
    const float* dt_proj_w  = (const float*)d_in[5];
    const float* dt_proj_b  = (const float*)d_in[6];
    const float* out_proj_w = (const float*)d_in[7];
    const float* A_log      = (const float*)d_in[8];
    const float* D_param    = (const float*)d_in[9];
    float* out = (float*)d_out;

    float *proj, *h, *ssm, *dt, *y;
    cudaGetSymbolAddress((void**)&proj, g_proj);
    cudaGetSymbolAddress((void**)&h,    g_h);
    cudaGetSymbolAddress((void**)&ssm,  g_ssm);
    cudaGetSymbolAddress((void**)&dt,   g_dt);
    cudaGetSymbolAddress((void**)&y,    g_y);

    // 1) proj = x @ in_proj_w   [4096,3072], K=768  (tf32 tensor cores)
    tgemm<0><<<dim3((2 * DIn) / 128, BLn / 128), 256>>>(
        x, Hn, in_proj_w, proj, 2 * DIn, Hn, nullptr);

    // 2) depthwise causal conv + SiLU -> g_h
    conv_silu<<<(BLn * DIn) / 256, 256>>>(proj, conv_w, conv_b, h);

    // 3) ssm = h @ x_proj_w   [4096,80], K=1536
    gemm_xproj<<<BLn / 32, 256>>>(h, x_proj_w, ssm);

    // 4) dt = softplus(ssm[:, :48] @ dt_proj_w + b)   [4096,1536], K=48
    tgemm<1><<<dim3(DIn / 128, BLn / 128), 256>>>(
        ssm, SP, dt_proj_w, dt, DIn, Rn, dt_proj_b);

    // 5) selective scan (+ skip + gating)
    scan_kernel<<<Bn * (DIn / 8), 128>>>(A_log, D_param);

    // 6) out = y @ out_proj_w   [4096,768], K=1536
    tgemm<0><<<dim3(Hn / 128, BLn / 128), 256>>>(
        y, DIn, out_proj_w, out, Hn, DIn, nullptr);
}